// round 2
// baseline (speedup 1.0000x reference)
#include <cuda_runtime.h>

// ---------------------------------------------------------------------------
// GATv2 (H=2, EMB=64) + fused final linear, collapsed to scalar-per-edge form.
// R2: edge-pair packing in f32x2 (EPT=8, ILP=8), head-split channel loop,
//     LDS.128 weight structs, 3-FMA self-loop path, merged init.
//
// Per-edge:  logit_h = 0.6*L_h + 0.4*sum_c att_hc*|z_hc|   (LeakyReLU split)
//            z_hc = s*Wl + t*Wr + a*We + b,  L_h = s*P_h + t*Q_h + a*R_h + B_h
// Per-node:  S_ih = sum_e alpha_eh * x[src_e]   (softmax without max-shift)
// Output:    out[i,:] = S_i0*A0 + S_i1*A1 + C   (rank-2, 128-wide)
// ---------------------------------------------------------------------------

#define NODE_CAP 131072
#define EPT 8
#define NPAIR 4

typedef unsigned long long u64;

__device__ float4 g_accum[NODE_CAP];    // {den0, num0, den1, num1}
__device__ float2 g_degattr[NODE_CAP];  // {deg, attr_sum}
__device__ float2 g_S[NODE_CAP];        // {S0, S1}

// channel-head-major (idx = h*64 + c), att & kap folded, values replicated in pack
__device__ ulonglong2 g_wa[128];  // {wl2, wr2}
__device__ ulonglong2 g_wb[128];  // {we2, b2}
__device__ u64 g_wlr[128];        // {wl+wr} for self-loop path
__device__ unsigned g_mk[128];    // sign mask of att (0x80000000 or 0)
__device__ u64 g_lp[2], g_lq[2], g_lr[2], g_lb[2];   // linear part per head (replicated pack)
__device__ u64 g_lpq[2];                              // P+Q per head (self loop)
__device__ __align__(16) float g_A0[128];
__device__ __align__(16) float g_A1[128];
__device__ __align__(16) float g_C[128];
__device__ int g_idx64;

// ---- f32x2 helpers ----
__device__ __forceinline__ u64 pack2(float lo, float hi) {
    u64 r;
    asm("mov.b64 %0, {%1, %2};" : "=l"(r) : "r"(__float_as_uint(lo)), "r"(__float_as_uint(hi)));
    return r;
}
__device__ __forceinline__ void unpack2(u64 v, float& lo, float& hi) {
    unsigned a, b;
    asm("mov.b64 {%0, %1}, %2;" : "=r"(a), "=r"(b) : "l"(v));
    lo = __uint_as_float(a); hi = __uint_as_float(b);
}
__device__ __forceinline__ u64 fma2(u64 a, u64 b, u64 c) {
    u64 d;
    asm("fma.rn.f32x2 %0, %1, %2, %3;" : "=l"(d) : "l"(a), "l"(b), "l"(c));
    return d;
}
__device__ __forceinline__ u64 add2(u64 a, u64 b) {
    u64 d;
    asm("add.rn.f32x2 %0, %1, %2;" : "=l"(d) : "l"(a), "l"(b));
    return d;
}
// per 32-bit half: (z & 0x7fffffff) | m   — |z| with sign(att) applied (ALU pipe)
__device__ __forceinline__ u64 abso2(u64 z, unsigned m) {
    unsigned lo, hi, rlo, rhi;
    asm("mov.b64 {%0, %1}, %2;" : "=r"(lo), "=r"(hi) : "l"(z));
    asm("lop3.b32 %0, %1, 0x7fffffff, %2, 0xEA;" : "=r"(rlo) : "r"(lo), "r"(m));
    asm("lop3.b32 %0, %1, 0x7fffffff, %2, 0xEA;" : "=r"(rhi) : "r"(hi), "r"(m));
    u64 r;
    asm("mov.b64 %0, {%1, %2};" : "=l"(r) : "r"(rlo), "r"(rhi));
    return r;
}
__device__ __forceinline__ float ex2f(float x) {
    float r;
    asm("ex2.approx.f32 %0, %1;" : "=f"(r) : "f"(x));
    return r;
}

// ---------------------------------------------------------------------------
// merged zero + weight prep (block 0 does prep)
__global__ void k_prep(const void* __restrict__ eidx, int n,
                       const float* __restrict__ Wl, const float* __restrict__ bl,
                       const float* __restrict__ Wr, const float* __restrict__ br,
                       const float* __restrict__ We, const float* __restrict__ att)
{
    int i = blockIdx.x * blockDim.x + threadIdx.x;
    if (i < n) {
        g_accum[i] = make_float4(0.f, 0.f, 0.f, 0.f);
        g_degattr[i] = make_float2(0.f, 0.f);
    }
    if (blockIdx.x == 0) {
        const float LOG2E = 1.4426950408889634f;
        const float kap = 0.4f * LOG2E;
        const float lam = 0.6f * LOG2E;
        int tid = threadIdx.x;
        if (tid < 128) {
            float aA = att[tid];
            float ka = kap * aA;
            float wl = ka * Wl[tid], wr = ka * Wr[tid], we = ka * We[tid];
            float bb = ka * (bl[tid] + br[tid]);
            ulonglong2 wa; wa.x = pack2(wl, wl); wa.y = pack2(wr, wr);
            ulonglong2 wb; wb.x = pack2(we, we); wb.y = pack2(bb, bb);
            g_wa[tid] = wa; g_wb[tid] = wb;
            float wlr = wl + wr;
            g_wlr[tid] = pack2(wlr, wlr);
            g_mk[tid] = __float_as_uint(aA) & 0x80000000u;
        }
        if (tid == 0) {
            for (int h = 0; h < 2; h++) {
                float P = 0, Q = 0, R = 0, B = 0;
                for (int c = 0; c < 64; c++) {
                    int j = h * 64 + c;
                    float aA = att[j];
                    P += aA * Wl[j]; Q += aA * Wr[j]; R += aA * We[j];
                    B += aA * (bl[j] + br[j]);
                }
                P *= lam; Q *= lam; R *= lam; B *= lam;
                g_lp[h] = pack2(P, P); g_lq[h] = pack2(Q, Q);
                g_lr[h] = pack2(R, R); g_lb[h] = pack2(B, B);
                float PQ = P + Q;
                g_lpq[h] = pack2(PQ, PQ);
            }
            // edge_index dtype detection
            const u64* p = (const u64*)eidx;
            int is64 = 1;
            for (int k = 0; k < 16; k++)
                if (p[k] >= (u64)n) is64 = 0;
            g_idx64 = is64;
        }
    }
}

// ---------------------------------------------------------------------------
__global__ void __launch_bounds__(256, 2) k_edges(
    const float* __restrict__ x, const void* __restrict__ eidx,
    const float* __restrict__ eattr, int E)
{
    __shared__ ulonglong2 s_wa[128], s_wb[128];
    __shared__ unsigned s_mk[128];
    int tid = threadIdx.x;
    if (tid < 128) { s_wa[tid] = g_wa[tid]; s_wb[tid] = g_wb[tid]; s_mk[tid] = g_mk[tid]; }
    __syncthreads();

    long long base = (long long)(blockIdx.x * blockDim.x + tid) * EPT;
    if (base >= E) return;
    int idx64 = g_idx64;
    const long long* p64 = (const long long*)eidx;
    const int* p32 = (const int*)eidx;

    int dst[EPT];
    float sv[EPT], tv[EPT], av[EPT];
#pragma unroll
    for (int k = 0; k < EPT; k++) {
        long long e = base + k; if (e > E - 1) e = E - 1;
        int si, di;
        if (idx64) { si = (int)p64[e]; di = (int)p64[E + e]; }
        else       { si = p32[e];      di = p32[E + e]; }
        dst[k] = di;
        av[k] = eattr[e];
        sv[k] = x[si];
        tv[k] = x[di];
    }
    // pack edge pairs
    u64 sp[NPAIR], tp[NPAIR], ap[NPAIR];
#pragma unroll
    for (int p = 0; p < NPAIR; p++) {
        sp[p] = pack2(sv[2 * p], sv[2 * p + 1]);
        tp[p] = pack2(tv[2 * p], tv[2 * p + 1]);
        ap[p] = pack2(av[2 * p], av[2 * p + 1]);
    }

    u64 acc0[NPAIR] = {0, 0, 0, 0};
    u64 acc1[NPAIR] = {0, 0, 0, 0};

    // head 0: channels 0..63
#pragma unroll 4
    for (int c = 0; c < 64; c++) {
        ulonglong2 wa = s_wa[c], wb = s_wb[c];
        unsigned m = s_mk[c];
#pragma unroll
        for (int p = 0; p < NPAIR; p++) {
            u64 z = fma2(ap[p], wb.x, wb.y);
            z = fma2(tp[p], wa.y, z);
            z = fma2(sp[p], wa.x, z);
            acc0[p] = add2(acc0[p], abso2(z, m));
        }
    }
    // head 1: channels 64..127
#pragma unroll 4
    for (int c = 64; c < 128; c++) {
        ulonglong2 wa = s_wa[c], wb = s_wb[c];
        unsigned m = s_mk[c];
#pragma unroll
        for (int p = 0; p < NPAIR; p++) {
            u64 z = fma2(ap[p], wb.x, wb.y);
            z = fma2(tp[p], wa.y, z);
            z = fma2(sp[p], wa.x, z);
            acc1[p] = add2(acc1[p], abso2(z, m));
        }
    }

    // epilogue: add linear part, exp2, atomics
    u64 P0 = g_lp[0], Q0 = g_lq[0], R0 = g_lr[0], B0 = g_lb[0];
    u64 P1 = g_lp[1], Q1 = g_lq[1], R1 = g_lr[1], B1 = g_lb[1];
    float e0v[EPT], e1v[EPT];
#pragma unroll
    for (int p = 0; p < NPAIR; p++) {
        u64 L0 = fma2(sp[p], P0, fma2(tp[p], Q0, fma2(ap[p], R0, B0)));
        u64 L1 = fma2(sp[p], P1, fma2(tp[p], Q1, fma2(ap[p], R1, B1)));
        u64 f0 = add2(acc0[p], L0);
        u64 f1 = add2(acc1[p], L1);
        float fa, fb;
        unpack2(f0, fa, fb); e0v[2 * p] = ex2f(fa); e0v[2 * p + 1] = ex2f(fb);
        unpack2(f1, fa, fb); e1v[2 * p] = ex2f(fa); e1v[2 * p + 1] = ex2f(fb);
    }
#pragma unroll
    for (int k = 0; k < EPT; k++) {
        if (base + k < E) {
            float e0 = e0v[k], e1 = e1v[k];
            atomicAdd(&g_degattr[dst[k]], make_float2(1.0f, av[k]));
            atomicAdd(&g_accum[dst[k]], make_float4(e0, e0 * sv[k], e1, e1 * sv[k]));
        }
    }
}

// ---------------------------------------------------------------------------
// self-loop contribution + finalize S = num/den  (2 nodes packed per lane)
__global__ void __launch_bounds__(256) k_nodes(const float* __restrict__ x, int n)
{
    __shared__ u64 s_wlr[128];
    __shared__ ulonglong2 s_wb[128];
    __shared__ unsigned s_mk[128];
    int tid = threadIdx.x;
    if (tid < 128) { s_wlr[tid] = g_wlr[tid]; s_wb[tid] = g_wb[tid]; s_mk[tid] = g_mk[tid]; }
    __syncthreads();

    int gid = blockIdx.x * blockDim.x + tid;
    int i0 = gid * 2;
    if (i0 >= n) return;
    int i1 = (i0 + 1 < n) ? i0 + 1 : i0;

    float sa = x[i0], sb = x[i1];
    float2 da0 = g_degattr[i0], da1 = g_degattr[i1];
    float am0 = da0.y / fmaxf(da0.x, 1.0f);
    float am1 = da1.y / fmaxf(da1.x, 1.0f);

    u64 s2 = pack2(sa, sb), a2 = pack2(am0, am1);
    u64 acc0 = 0ull, acc1 = 0ull;
#pragma unroll 8
    for (int c = 0; c < 64; c++) {
        ulonglong2 wb = s_wb[c];
        u64 z = fma2(a2, wb.x, wb.y);
        z = fma2(s2, s_wlr[c], z);
        acc0 = add2(acc0, abso2(z, s_mk[c]));
    }
#pragma unroll 8
    for (int c = 64; c < 128; c++) {
        ulonglong2 wb = s_wb[c];
        u64 z = fma2(a2, wb.x, wb.y);
        z = fma2(s2, s_wlr[c], z);
        acc1 = add2(acc1, abso2(z, s_mk[c]));
    }
    u64 f0 = add2(acc0, fma2(s2, g_lpq[0], fma2(a2, g_lr[0], g_lb[0])));
    u64 f1 = add2(acc1, fma2(s2, g_lpq[1], fma2(a2, g_lr[1], g_lb[1])));
    float f0a, f0b, f1a, f1b;
    unpack2(f0, f0a, f0b);
    unpack2(f1, f1a, f1b);
    float ea0 = ex2f(f0a), eb0 = ex2f(f0b);
    float ea1 = ex2f(f1a), eb1 = ex2f(f1b);

    float4 ac = g_accum[i0];
    g_S[i0] = make_float2((ac.y + ea0 * sa) / (ac.x + ea0),
                          (ac.w + ea1 * sa) / (ac.z + ea1));
    if (i0 + 1 < n) {
        float4 ac1 = g_accum[i1];
        g_S[i1] = make_float2((ac1.y + eb0 * sb) / (ac1.x + eb0),
                              (ac1.w + eb1 * sb) / (ac1.z + eb1));
    }
}

// ---------------------------------------------------------------------------
// A0, A1, C vectors (needs S[target])
__global__ void k_vec(const float* __restrict__ Wl, const float* __restrict__ bl,
                      const float* __restrict__ bout, const float* __restrict__ Wfc,
                      const float* __restrict__ bfc, const int* __restrict__ tgtp)
{
    int j = threadIdx.x;  // 0..127
    if (j >= 128) return;
    int tgt = tgtp[0];    // low 32 bits valid for int32 or int64 (little-endian)
    float2 st = g_S[tgt];
    const float* wrow = Wfc + j * 256;

    float a0 = 0.f, a1 = 0.f;
    for (int c = 0; c < 64; c++) {
        a0 += Wl[c] * wrow[c];
        a1 += Wl[64 + c] * wrow[64 + c];
    }
    float cc = bfc[j];
    for (int k = 0; k < 128; k++) {
        float cst = bl[k] + bout[k];
        cc += cst * wrow[k];
        float sh = (k < 64) ? st.x : st.y;
        float tg = Wl[k] * sh + cst;
        cc += tg * wrow[128 + k];
    }
    g_A0[j] = a0; g_A1[j] = a1; g_C[j] = cc;
}

// ---------------------------------------------------------------------------
// out[i, 0:128] = S0*A0 + S1*A1 + C  — one warp per node, float4 stores
__global__ void __launch_bounds__(256) k_out(float* __restrict__ out, int n)
{
    int lane = threadIdx.x & 31;
    int warp = (blockIdx.x * blockDim.x + threadIdx.x) >> 5;
    int nwarps = (gridDim.x * blockDim.x) >> 5;
    float4 A0v = ((const float4*)g_A0)[lane];
    float4 A1v = ((const float4*)g_A1)[lane];
    float4 Cv  = ((const float4*)g_C)[lane];
    float4* o4 = (float4*)out;
    for (int i = warp; i < n; i += nwarps) {
        float2 s = g_S[i];
        float4 o;
        o.x = fmaf(s.x, A0v.x, fmaf(s.y, A1v.x, Cv.x));
        o.y = fmaf(s.x, A0v.y, fmaf(s.y, A1v.y, Cv.y));
        o.z = fmaf(s.x, A0v.z, fmaf(s.y, A1v.z, Cv.z));
        o.w = fmaf(s.x, A0v.w, fmaf(s.y, A1v.w, Cv.w));
        o4[i * 32 + lane] = o;
    }
}

// ---------------------------------------------------------------------------
extern "C" void kernel_launch(void* const* d_in, const int* in_sizes, int n_in,
                              void* d_out, int out_size)
{
    const float* x     = (const float*)d_in[0];
    const void*  eidx  = d_in[1];
    const float* eattr = (const float*)d_in[2];
    const int*   tgtp  = (const int*)d_in[3];
    const float* Wl    = (const float*)d_in[4];
    const float* bl    = (const float*)d_in[5];
    const float* Wr    = (const float*)d_in[6];
    const float* br    = (const float*)d_in[7];
    const float* We    = (const float*)d_in[8];
    const float* att   = (const float*)d_in[9];
    const float* bout  = (const float*)d_in[10];
    const float* Wfc   = (const float*)d_in[11];
    const float* bfc   = (const float*)d_in[12];

    int n = in_sizes[0];   // N nodes (x is [N,1])
    int E = in_sizes[2];   // edges (edge_attr is [E,1])
    float* out = (float*)d_out;

    k_prep<<<(n + 255) / 256, 256>>>(eidx, n, Wl, bl, Wr, br, We, att);
    int ethreads = (E + EPT - 1) / EPT;
    k_edges<<<(ethreads + 255) / 256, 256>>>(x, eidx, eattr, E);
    int nthreads = (n + 1) / 2;
    k_nodes<<<(nthreads + 255) / 256, 256>>>(x, n);
    k_vec<<<1, 128>>>(Wl, bl, bout, Wfc, bfc, tgtp);
    k_out<<<1184, 256>>>(out, n);
}

// round 6
// speedup vs baseline: 1.4293x; 1.4293x over previous
#include <cuda_runtime.h>

// ---------------------------------------------------------------------------
// GATv2 (H=2, EMB=64) + fused final linear, collapsed to scalar-per-edge form.
// R3: parallel weight-prep for final linear (was 33.5us single-block kernel),
//     rank-2 target fold into k_out, edges reverted to R1 structure (EPT=4,
//     head-packed f32x2), R2 nodes kept.
//
// Per-edge:  logit_h = 0.6*L_h + 0.4*sum_c att_hc*|z_hc|   (LeakyReLU split)
//            z_hc = s*Wl + t*Wr + a*We + b,  L_h = s*P_h + t*Q_h + a*R_h + B_h
// Per-node:  S_ih = sum_e alpha_eh * x[src_e]   (softmax without max-shift)
// Output:    out[i,:] = S_i0*A0 + S_i1*A1 + (Cbase + T0*D0 + T1*D1)
// ---------------------------------------------------------------------------

#define NODE_CAP 131072
#define EPT 4

typedef unsigned long long u64;

__device__ float4 g_accum[NODE_CAP];    // {den0, num0, den1, num1}
__device__ float2 g_degattr[NODE_CAP];  // {deg, attr_sum}
__device__ float2 g_S[NODE_CAP];        // {S0, S1}

// --- edge-kernel weights: head-packed f32x2 (lo=head0, hi=head1), idx=c<64
__device__ u64 g_wlA[64], g_wrA[64], g_weA[64], g_bA[64], g_sm[64];
__device__ u64 g_lin[4];   // P, Q, R, B head-packed

// --- node-kernel weights: head-split (idx = h*64+c), node-pair replicated pack
__device__ u64 g_nwlr[128];        // wl+wr replicated
__device__ ulonglong2 g_nwb[128];  // {we2, b2} replicated
__device__ unsigned g_nmk[128];    // sign mask of att
__device__ u64 g_nlpq[2], g_nlr[2], g_nlb[2];

// --- final linear vectors
__device__ __align__(16) float g_A0[128];
__device__ __align__(16) float g_A1[128];
__device__ __align__(16) float g_CB[128];
__device__ __align__(16) float g_D0[128];
__device__ __align__(16) float g_D1[128];
__device__ int g_idx64;

// ---- f32x2 helpers ----
__device__ __forceinline__ u64 pack2(float lo, float hi) {
    u64 r;
    asm("mov.b64 %0, {%1, %2};" : "=l"(r) : "r"(__float_as_uint(lo)), "r"(__float_as_uint(hi)));
    return r;
}
__device__ __forceinline__ void unpack2(u64 v, float& lo, float& hi) {
    unsigned a, b;
    asm("mov.b64 {%0, %1}, %2;" : "=r"(a), "=r"(b) : "l"(v));
    lo = __uint_as_float(a); hi = __uint_as_float(b);
}
__device__ __forceinline__ u64 fma2(u64 a, u64 b, u64 c) {
    u64 d;
    asm("fma.rn.f32x2 %0, %1, %2, %3;" : "=l"(d) : "l"(a), "l"(b), "l"(c));
    return d;
}
__device__ __forceinline__ u64 add2(u64 a, u64 b) {
    u64 d;
    asm("add.rn.f32x2 %0, %1, %2;" : "=l"(d) : "l"(a), "l"(b));
    return d;
}
// per 32-bit half: (z & 0x7fffffff) | mask   (LOP3, immLut 0xEA)
__device__ __forceinline__ u64 abso2(u64 z, unsigned mlo, unsigned mhi) {
    unsigned lo, hi, rlo, rhi;
    asm("mov.b64 {%0, %1}, %2;" : "=r"(lo), "=r"(hi) : "l"(z));
    asm("lop3.b32 %0, %1, 0x7fffffff, %2, 0xEA;" : "=r"(rlo) : "r"(lo), "r"(mlo));
    asm("lop3.b32 %0, %1, 0x7fffffff, %2, 0xEA;" : "=r"(rhi) : "r"(hi), "r"(mhi));
    u64 r;
    asm("mov.b64 %0, {%1, %2};" : "=l"(r) : "r"(rlo), "r"(rhi));
    return r;
}
__device__ __forceinline__ float ex2f(float x) {
    float r;
    asm("ex2.approx.f32 %0, %1;" : "=f"(r) : "f"(x));
    return r;
}

// ---------------------------------------------------------------------------
// merged zero + weight prep (block 0 does prep)
__global__ void k_prep(const void* __restrict__ eidx, int n,
                       const float* __restrict__ Wl, const float* __restrict__ bl,
                       const float* __restrict__ Wr, const float* __restrict__ br,
                       const float* __restrict__ We, const float* __restrict__ att)
{
    int i = blockIdx.x * blockDim.x + threadIdx.x;
    if (i < n) {
        g_accum[i] = make_float4(0.f, 0.f, 0.f, 0.f);
        g_degattr[i] = make_float2(0.f, 0.f);
    }
    if (blockIdx.x == 0) {
        const float LOG2E = 1.4426950408889634f;
        const float kap = 0.4f * LOG2E;
        const float lam = 0.6f * LOG2E;
        int tid = threadIdx.x;
        if (tid < 64) {   // edge layout: head-packed
            int c = tid;
            float a0 = att[c], a1 = att[64 + c];
            float b0 = bl[c] + br[c], b1 = bl[64 + c] + br[64 + c];
            g_wlA[c] = pack2(kap * a0 * Wl[c], kap * a1 * Wl[64 + c]);
            g_wrA[c] = pack2(kap * a0 * Wr[c], kap * a1 * Wr[64 + c]);
            g_weA[c] = pack2(kap * a0 * We[c], kap * a1 * We[64 + c]);
            g_bA[c]  = pack2(kap * a0 * b0,    kap * a1 * b1);
            unsigned m0 = __float_as_uint(a0) & 0x80000000u;
            unsigned m1 = __float_as_uint(a1) & 0x80000000u;
            g_sm[c] = ((u64)m1 << 32) | (u64)m0;
        }
        if (tid < 128) {  // node layout: head-split, replicated pack
            float aA = att[tid];
            float ka = kap * aA;
            float wl = ka * Wl[tid], wr = ka * Wr[tid], we = ka * We[tid];
            float bb = ka * (bl[tid] + br[tid]);
            float wlr = wl + wr;
            g_nwlr[tid] = pack2(wlr, wlr);
            ulonglong2 wb; wb.x = pack2(we, we); wb.y = pack2(bb, bb);
            g_nwb[tid] = wb;
            g_nmk[tid] = __float_as_uint(aA) & 0x80000000u;
        }
        if (tid == 0) {
            float Ph[2], Qh[2], Rh[2], Bh[2];
            for (int h = 0; h < 2; h++) {
                float P = 0, Q = 0, R = 0, B = 0;
                for (int c = 0; c < 64; c++) {
                    int j = h * 64 + c;
                    float aA = att[j];
                    P += aA * Wl[j]; Q += aA * Wr[j]; R += aA * We[j];
                    B += aA * (bl[j] + br[j]);
                }
                Ph[h] = lam * P; Qh[h] = lam * Q; Rh[h] = lam * R; Bh[h] = lam * B;
            }
            g_lin[0] = pack2(Ph[0], Ph[1]);
            g_lin[1] = pack2(Qh[0], Qh[1]);
            g_lin[2] = pack2(Rh[0], Rh[1]);
            g_lin[3] = pack2(Bh[0], Bh[1]);
            for (int h = 0; h < 2; h++) {
                float PQ = Ph[h] + Qh[h];
                g_nlpq[h] = pack2(PQ, PQ);
                g_nlr[h]  = pack2(Rh[h], Rh[h]);
                g_nlb[h]  = pack2(Bh[h], Bh[h]);
            }
            // edge_index dtype detection (int64 values all < n)
            const u64* p = (const u64*)eidx;
            int is64 = 1;
            for (int k = 0; k < 16; k++)
                if (p[k] >= (u64)n) is64 = 0;
            g_idx64 = is64;
        }
    }
}

// ---------------------------------------------------------------------------
// Final-linear vectors from weights only (no S dependence).
// One warp per output row j (128 warps). Coalesced Wfc loads + shfl reduce.
__global__ void __launch_bounds__(256) k_vecA(
    const float* __restrict__ Wl, const float* __restrict__ bl,
    const float* __restrict__ bout, const float* __restrict__ Wfc,
    const float* __restrict__ bfc)
{
    int lane = threadIdx.x & 31;
    int j = (blockIdx.x * blockDim.x + threadIdx.x) >> 5;
    if (j >= 128) return;
    const float* wrow = Wfc + j * 256;

    float a0 = 0.f, a1 = 0.f, cb = 0.f, d0 = 0.f, d1 = 0.f;
#pragma unroll
    for (int u = 0; u < 8; u++) {
        int idx = u * 32 + lane;
        float w = wrow[idx];
        if (u < 2) {                       // idx 0..63
            a0 += Wl[idx] * w;
            cb += (bl[idx] + bout[idx]) * w;
        } else if (u < 4) {                // idx 64..127
            a1 += Wl[idx] * w;
            cb += (bl[idx] + bout[idx]) * w;
        } else if (u < 6) {                // idx 128..191 -> kk 0..63
            int kk = idx - 128;
            cb += (bl[kk] + bout[kk]) * w;
            d0 += Wl[kk] * w;
        } else {                           // idx 192..255 -> kk 64..127
            int kk = idx - 128;
            cb += (bl[kk] + bout[kk]) * w;
            d1 += Wl[kk] * w;
        }
    }
#pragma unroll
    for (int off = 16; off > 0; off >>= 1) {
        a0 += __shfl_xor_sync(0xffffffffu, a0, off);
        a1 += __shfl_xor_sync(0xffffffffu, a1, off);
        cb += __shfl_xor_sync(0xffffffffu, cb, off);
        d0 += __shfl_xor_sync(0xffffffffu, d0, off);
        d1 += __shfl_xor_sync(0xffffffffu, d1, off);
    }
    if (lane == 0) {
        g_A0[j] = a0; g_A1[j] = a1; g_CB[j] = cb + bfc[j];
        g_D0[j] = d0; g_D1[j] = d1;
    }
}

// ---------------------------------------------------------------------------
// Edge pass (R1 structure: head-packed f32x2, EPT=4)
__global__ void __launch_bounds__(256) k_edges(
    const float* __restrict__ x, const void* __restrict__ eidx,
    const float* __restrict__ eattr, int E)
{
    __shared__ u64 s_wl[64], s_wr[64], s_we[64], s_b[64], s_m[64];
    int tid = threadIdx.x;
    if (tid < 64) {
        s_wl[tid] = g_wlA[tid]; s_wr[tid] = g_wrA[tid]; s_we[tid] = g_weA[tid];
        s_b[tid]  = g_bA[tid];  s_m[tid]  = g_sm[tid];
    }
    __syncthreads();

    int base = (blockIdx.x * blockDim.x + tid) * EPT;
    if (base >= E) return;
    int idx64 = g_idx64;
    const long long* p64 = (const long long*)eidx;
    const int* p32 = (const int*)eidx;

    float sv[EPT], av[EPT];
    u64 s2[EPT], t2[EPT], a2[EPT], acc[EPT];
    int dsti[EPT];
    bool ok[EPT];

#pragma unroll
    for (int k = 0; k < EPT; k++) {
        int e = base + k;
        ok[k] = (e < E);
        int si = 0, di = 0;
        float aa = 0.f, s = 0.f, t = 0.f;
        if (ok[k]) {
            if (idx64) { si = (int)p64[e]; di = (int)p64[E + e]; }
            else       { si = p32[e];      di = p32[E + e]; }
            aa = eattr[e];
            s = x[si]; t = x[di];
        }
        dsti[k] = di; sv[k] = s; av[k] = aa;
        s2[k] = pack2(s, s); t2[k] = pack2(t, t); a2[k] = pack2(aa, aa);
        acc[k] = 0ull;
    }

#pragma unroll 8
    for (int c = 0; c < 64; c++) {
        u64 wl = s_wl[c], wr = s_wr[c], we = s_we[c], bb = s_b[c];
        u64 mm = s_m[c];
        unsigned mlo = (unsigned)mm, mhi = (unsigned)(mm >> 32);
#pragma unroll
        for (int k = 0; k < EPT; k++) {
            u64 z = fma2(a2[k], we, bb);
            z = fma2(t2[k], wr, z);
            z = fma2(s2[k], wl, z);
            acc[k] = add2(acc[k], abso2(z, mlo, mhi));
        }
    }

    u64 P = g_lin[0], Q = g_lin[1], R = g_lin[2], B = g_lin[3];
#pragma unroll
    for (int k = 0; k < EPT; k++) {
        if (!ok[k]) continue;
        u64 f2 = add2(acc[k], B);
        f2 = fma2(a2[k], R, f2);
        f2 = fma2(t2[k], Q, f2);
        f2 = fma2(s2[k], P, f2);
        float f0, f1; unpack2(f2, f0, f1);
        float e0 = ex2f(f0), e1 = ex2f(f1);
        atomicAdd(&g_degattr[dsti[k]], make_float2(1.0f, av[k]));
        atomicAdd(&g_accum[dsti[k]], make_float4(e0, e0 * sv[k], e1, e1 * sv[k]));
    }
}

// ---------------------------------------------------------------------------
// self-loop contribution + finalize S = num/den  (2 nodes packed per lane)
__global__ void __launch_bounds__(256) k_nodes(const float* __restrict__ x, int n)
{
    __shared__ u64 s_wlr[128];
    __shared__ ulonglong2 s_wb[128];
    __shared__ unsigned s_mk[128];
    int tid = threadIdx.x;
    if (tid < 128) { s_wlr[tid] = g_nwlr[tid]; s_wb[tid] = g_nwb[tid]; s_mk[tid] = g_nmk[tid]; }
    __syncthreads();

    int gid = blockIdx.x * blockDim.x + tid;
    int i0 = gid * 2;
    if (i0 >= n) return;
    int i1 = (i0 + 1 < n) ? i0 + 1 : i0;

    float sa = x[i0], sb = x[i1];
    float2 da0 = g_degattr[i0], da1 = g_degattr[i1];
    float am0 = da0.y / fmaxf(da0.x, 1.0f);
    float am1 = da1.y / fmaxf(da1.x, 1.0f);

    u64 s2 = pack2(sa, sb), a2 = pack2(am0, am1);
    u64 acc0 = 0ull, acc1 = 0ull;
#pragma unroll 8
    for (int c = 0; c < 64; c++) {
        ulonglong2 wb = s_wb[c];
        u64 z = fma2(a2, wb.x, wb.y);
        z = fma2(s2, s_wlr[c], z);
        acc0 = add2(acc0, abso2(z, s_mk[c], s_mk[c]));
    }
#pragma unroll 8
    for (int c = 64; c < 128; c++) {
        ulonglong2 wb = s_wb[c];
        u64 z = fma2(a2, wb.x, wb.y);
        z = fma2(s2, s_wlr[c], z);
        acc1 = add2(acc1, abso2(z, s_mk[c], s_mk[c]));
    }
    u64 f0 = add2(acc0, fma2(s2, g_nlpq[0], fma2(a2, g_nlr[0], g_nlb[0])));
    u64 f1 = add2(acc1, fma2(s2, g_nlpq[1], fma2(a2, g_nlr[1], g_nlb[1])));
    float f0a, f0b, f1a, f1b;
    unpack2(f0, f0a, f0b);
    unpack2(f1, f1a, f1b);
    float ea0 = ex2f(f0a), eb0 = ex2f(f0b);
    float ea1 = ex2f(f1a), eb1 = ex2f(f1b);

    float4 ac = g_accum[i0];
    g_S[i0] = make_float2((ac.y + ea0 * sa) / (ac.x + ea0),
                          (ac.w + ea1 * sa) / (ac.z + ea1));
    if (i0 + 1 < n) {
        float4 ac1 = g_accum[i1];
        g_S[i1] = make_float2((ac1.y + eb0 * sb) / (ac1.x + eb0),
                              (ac1.w + eb1 * sb) / (ac1.z + eb1));
    }
}

// ---------------------------------------------------------------------------
// out[i, 0:128] = S0*A0 + S1*A1 + (CB + T0*D0 + T1*D1) — warp per node
__global__ void __launch_bounds__(256) k_out(float* __restrict__ out, int n,
                                             const int* __restrict__ tgtp)
{
    int lane = threadIdx.x & 31;
    int warp = (blockIdx.x * blockDim.x + threadIdx.x) >> 5;
    int nwarps = (gridDim.x * blockDim.x) >> 5;
    int tgt = tgtp[0];           // low 32 bits valid for int32/int64 (LE)
    float2 st = g_S[tgt];
    float4 A0v = ((const float4*)g_A0)[lane];
    float4 A1v = ((const float4*)g_A1)[lane];
    float4 CBv = ((const float4*)g_CB)[lane];
    float4 D0v = ((const float4*)g_D0)[lane];
    float4 D1v = ((const float4*)g_D1)[lane];
    float4 Cv;
    Cv.x = fmaf(st.x, D0v.x, fmaf(st.y, D1v.x, CBv.x));
    Cv.y = fmaf(st.x, D0v.y, fmaf(st.y, D1v.y, CBv.y));
    Cv.z = fmaf(st.x, D0v.z, fmaf(st.y, D1v.z, CBv.z));
    Cv.w = fmaf(st.x, D0v.w, fmaf(st.y, D1v.w, CBv.w));
    float4* o4 = (float4*)out;
    for (int i = warp; i < n; i += nwarps) {
        float2 s = g_S[i];
        float4 o;
        o.x = fmaf(s.x, A0v.x, fmaf(s.y, A1v.x, Cv.x));
        o.y = fmaf(s.x, A0v.y, fmaf(s.y, A1v.y, Cv.y));
        o.z = fmaf(s.x, A0v.z, fmaf(s.y, A1v.z, Cv.z));
        o.w = fmaf(s.x, A0v.w, fmaf(s.y, A1v.w, Cv.w));
        o4[i * 32 + lane] = o;
    }
}

// ---------------------------------------------------------------------------
extern "C" void kernel_launch(void* const* d_in, const int* in_sizes, int n_in,
                              void* d_out, int out_size)
{
    const float* x     = (const float*)d_in[0];
    const void*  eidx  = d_in[1];
    const float* eattr = (const float*)d_in[2];
    const int*   tgtp  = (const int*)d_in[3];
    const float* Wl    = (const float*)d_in[4];
    const float* bl    = (const float*)d_in[5];
    const float* Wr    = (const float*)d_in[6];
    const float* br    = (const float*)d_in[7];
    const float* We    = (const float*)d_in[8];
    const float* att   = (const float*)d_in[9];
    const float* bout  = (const float*)d_in[10];
    const float* Wfc   = (const float*)d_in[11];
    const float* bfc   = (const float*)d_in[12];

    int n = in_sizes[0];   // N nodes (x is [N,1])
    int E = in_sizes[2];   // edges (edge_attr is [E,1])
    float* out = (float*)d_out;

    k_prep<<<(n + 255) / 256, 256>>>(eidx, n, Wl, bl, Wr, br, We, att);
    k_vecA<<<16, 256>>>(Wl, bl, bout, Wfc, bfc);
    int ethreads = (E + EPT - 1) / EPT;
    k_edges<<<(ethreads + 255) / 256, 256>>>(x, eidx, eattr, E);
    int nthreads = (n + 1) / 2;
    k_nodes<<<(nthreads + 255) / 256, 256>>>(x, n);
    k_out<<<1184, 256>>>(out, n, tgtp);
}

// round 7
// speedup vs baseline: 1.4599x; 1.0214x over previous
#include <cuda_runtime.h>

// ---------------------------------------------------------------------------
// GATv2 (H=2, EMB=64) + fused final linear, collapsed to scalar-per-edge form.
// R7: fused nodes+out kernel, head-packed node weights, packed LDS.128 weight
//     structs in edge kernel, launch order puts k_edges at profile index 3.
//
// Per-edge:  logit_h = 0.6*L_h + 0.4*sum_c att_hc*|z_hc|   (LeakyReLU split)
//            z_hc = s*Wl + t*Wr + a*We + b,  L_h = s*P_h + t*Q_h + a*R_h + B_h
// Per-node:  S_ih = sum_e alpha_eh * x[src_e]   (softmax without max-shift)
// Output:    out[i,:] = S_i0*A0 + S_i1*A1 + (CB + T0*D0 + T1*D1)
// ---------------------------------------------------------------------------

#define NODE_CAP 131072
#define EPT 4

typedef unsigned long long u64;

__device__ float4 g_accum[NODE_CAP];    // {den0, num0, den1, num1}
__device__ float2 g_degattr[NODE_CAP];  // {deg, attr_sum}

// --- edge weights, head-packed f32x2 (lo=head0, hi=head1), idx c<64
__device__ ulonglong2 g_eA[64];   // {wl2, wr2}
__device__ ulonglong2 g_eB[64];   // {we2, b2}
__device__ u64 g_em[64];          // per-half sign masks of att
__device__ u64 g_lin[4];          // P, Q, R, B head-packed

// --- node (self-loop) weights, head-packed, idx c<64
__device__ ulonglong2 g_nA[64];   // {wlr2, we2}
__device__ ulonglong2 g_nB[64];   // {b2, m2}
__device__ u64 g_nlpq, g_nlr, g_nlb;

// --- final linear vectors
__device__ __align__(16) float g_A0[128];
__device__ __align__(16) float g_A1[128];
__device__ __align__(16) float g_CB[128];
__device__ __align__(16) float g_D0[128];
__device__ __align__(16) float g_D1[128];
__device__ __align__(16) float g_Cv[128];   // CB + T0*D0 + T1*D1 (k_tgt)
__device__ int g_idx64;

// ---- f32x2 helpers ----
__device__ __forceinline__ u64 pack2(float lo, float hi) {
    u64 r;
    asm("mov.b64 %0, {%1, %2};" : "=l"(r) : "r"(__float_as_uint(lo)), "r"(__float_as_uint(hi)));
    return r;
}
__device__ __forceinline__ void unpack2(u64 v, float& lo, float& hi) {
    unsigned a, b;
    asm("mov.b64 {%0, %1}, %2;" : "=r"(a), "=r"(b) : "l"(v));
    lo = __uint_as_float(a); hi = __uint_as_float(b);
}
__device__ __forceinline__ u64 fma2(u64 a, u64 b, u64 c) {
    u64 d;
    asm("fma.rn.f32x2 %0, %1, %2, %3;" : "=l"(d) : "l"(a), "l"(b), "l"(c));
    return d;
}
__device__ __forceinline__ u64 add2(u64 a, u64 b) {
    u64 d;
    asm("add.rn.f32x2 %0, %1, %2;" : "=l"(d) : "l"(a), "l"(b));
    return d;
}
// per 32-bit half: (z & 0x7fffffff) | mask   (LOP3, immLut 0xEA)
__device__ __forceinline__ u64 abso2(u64 z, unsigned mlo, unsigned mhi) {
    unsigned lo, hi, rlo, rhi;
    asm("mov.b64 {%0, %1}, %2;" : "=r"(lo), "=r"(hi) : "l"(z));
    asm("lop3.b32 %0, %1, 0x7fffffff, %2, 0xEA;" : "=r"(rlo) : "r"(lo), "r"(mlo));
    asm("lop3.b32 %0, %1, 0x7fffffff, %2, 0xEA;" : "=r"(rhi) : "r"(hi), "r"(mhi));
    u64 r;
    asm("mov.b64 %0, {%1, %2};" : "=l"(r) : "r"(rlo), "r"(rhi));
    return r;
}
__device__ __forceinline__ float ex2f(float x) {
    float r;
    asm("ex2.approx.f32 %0, %1;" : "=f"(r) : "f"(x));
    return r;
}

// ---------------------------------------------------------------------------
// launch 0: zero accumulators
__global__ void __launch_bounds__(256) k_zero(int n)
{
    int i = blockIdx.x * blockDim.x + threadIdx.x;
    if (i < n) {
        g_accum[i] = make_float4(0.f, 0.f, 0.f, 0.f);
        g_degattr[i] = make_float2(0.f, 0.f);
    }
}

// ---------------------------------------------------------------------------
// launch 1: weight prep (1 block, 128 threads)
__global__ void k_wprep(const void* __restrict__ eidx, int n,
                        const float* __restrict__ Wl, const float* __restrict__ bl,
                        const float* __restrict__ Wr, const float* __restrict__ br,
                        const float* __restrict__ We, const float* __restrict__ att)
{
    const float LOG2E = 1.4426950408889634f;
    const float kap = 0.4f * LOG2E;
    const float lam = 0.6f * LOG2E;
    int tid = threadIdx.x;
    if (tid < 64) {
        int c = tid;
        float a0 = att[c], a1 = att[64 + c];
        float k0 = kap * a0, k1 = kap * a1;
        float wl0 = k0 * Wl[c], wl1 = k1 * Wl[64 + c];
        float wr0 = k0 * Wr[c], wr1 = k1 * Wr[64 + c];
        float we0 = k0 * We[c], we1 = k1 * We[64 + c];
        float b0 = k0 * (bl[c] + br[c]), b1 = k1 * (bl[64 + c] + br[64 + c]);
        unsigned m0 = __float_as_uint(a0) & 0x80000000u;
        unsigned m1 = __float_as_uint(a1) & 0x80000000u;
        u64 m2 = ((u64)m1 << 32) | (u64)m0;
        ulonglong2 eA; eA.x = pack2(wl0, wl1); eA.y = pack2(wr0, wr1);
        ulonglong2 eB; eB.x = pack2(we0, we1); eB.y = pack2(b0, b1);
        g_eA[c] = eA; g_eB[c] = eB; g_em[c] = m2;
        ulonglong2 nA; nA.x = pack2(wl0 + wr0, wl1 + wr1); nA.y = eB.x;
        ulonglong2 nB; nB.x = eB.y; nB.y = m2;
        g_nA[c] = nA; g_nB[c] = nB;
    }
    if (tid == 0) {
        float Ph[2], Qh[2], Rh[2], Bh[2];
        for (int h = 0; h < 2; h++) {
            float P = 0, Q = 0, R = 0, B = 0;
            for (int c = 0; c < 64; c++) {
                int j = h * 64 + c;
                float aA = att[j];
                P += aA * Wl[j]; Q += aA * Wr[j]; R += aA * We[j];
                B += aA * (bl[j] + br[j]);
            }
            Ph[h] = lam * P; Qh[h] = lam * Q; Rh[h] = lam * R; Bh[h] = lam * B;
        }
        g_lin[0] = pack2(Ph[0], Ph[1]);
        g_lin[1] = pack2(Qh[0], Qh[1]);
        g_lin[2] = pack2(Rh[0], Rh[1]);
        g_lin[3] = pack2(Bh[0], Bh[1]);
        g_nlpq = pack2(Ph[0] + Qh[0], Ph[1] + Qh[1]);
        g_nlr  = g_lin[2];
        g_nlb  = g_lin[3];
        // edge_index dtype detection (int64 values all < n)
        const u64* p = (const u64*)eidx;
        int is64 = 1;
        for (int k = 0; k < 16; k++)
            if (p[k] >= (u64)n) is64 = 0;
        g_idx64 = is64;
    }
}

// ---------------------------------------------------------------------------
// launch 2: final-linear vectors (weights-only). Warp per output row.
__global__ void __launch_bounds__(256) k_vecA(
    const float* __restrict__ Wl, const float* __restrict__ bl,
    const float* __restrict__ bout, const float* __restrict__ Wfc,
    const float* __restrict__ bfc)
{
    int lane = threadIdx.x & 31;
    int j = (blockIdx.x * blockDim.x + threadIdx.x) >> 5;
    if (j >= 128) return;
    const float* wrow = Wfc + j * 256;

    float a0 = 0.f, a1 = 0.f, cb = 0.f, d0 = 0.f, d1 = 0.f;
#pragma unroll
    for (int u = 0; u < 8; u++) {
        int idx = u * 32 + lane;
        float w = wrow[idx];
        if (u < 2) {
            a0 += Wl[idx] * w;
            cb += (bl[idx] + bout[idx]) * w;
        } else if (u < 4) {
            a1 += Wl[idx] * w;
            cb += (bl[idx] + bout[idx]) * w;
        } else if (u < 6) {
            int kk = idx - 128;
            cb += (bl[kk] + bout[kk]) * w;
            d0 += Wl[kk] * w;
        } else {
            int kk = idx - 128;
            cb += (bl[kk] + bout[kk]) * w;
            d1 += Wl[kk] * w;
        }
    }
#pragma unroll
    for (int off = 16; off > 0; off >>= 1) {
        a0 += __shfl_xor_sync(0xffffffffu, a0, off);
        a1 += __shfl_xor_sync(0xffffffffu, a1, off);
        cb += __shfl_xor_sync(0xffffffffu, cb, off);
        d0 += __shfl_xor_sync(0xffffffffu, d0, off);
        d1 += __shfl_xor_sync(0xffffffffu, d1, off);
    }
    if (lane == 0) {
        g_A0[j] = a0; g_A1[j] = a1; g_CB[j] = cb + bfc[j];
        g_D0[j] = d0; g_D1[j] = d1;
    }
}

// ---------------------------------------------------------------------------
// launch 3 (PROFILED): edge pass
__global__ void __launch_bounds__(256, 2) k_edges(
    const float* __restrict__ x, const void* __restrict__ eidx,
    const float* __restrict__ eattr, int E)
{
    __shared__ ulonglong2 s_eA[64], s_eB[64];
    __shared__ u64 s_m[64];
    int tid = threadIdx.x;
    if (tid < 64) { s_eA[tid] = g_eA[tid]; s_eB[tid] = g_eB[tid]; s_m[tid] = g_em[tid]; }
    __syncthreads();

    int base = (blockIdx.x * blockDim.x + tid) * EPT;
    if (base >= E) return;
    int idx64 = g_idx64;
    const long long* p64 = (const long long*)eidx;
    const int* p32 = (const int*)eidx;

    float sv[EPT], av[EPT];
    u64 s2[EPT], t2[EPT], a2[EPT], acc[EPT];
    int dsti[EPT];
    bool ok[EPT];

#pragma unroll
    for (int k = 0; k < EPT; k++) {
        int e = base + k;
        ok[k] = (e < E);
        int si = 0, di = 0;
        float aa = 0.f, s = 0.f, t = 0.f;
        if (ok[k]) {
            if (idx64) { si = (int)p64[e]; di = (int)p64[E + e]; }
            else       { si = p32[e];      di = p32[E + e]; }
            aa = eattr[e];
            s = x[si]; t = x[di];
        }
        dsti[k] = di; sv[k] = s; av[k] = aa;
        s2[k] = pack2(s, s); t2[k] = pack2(t, t); a2[k] = pack2(aa, aa);
        acc[k] = 0ull;
    }

#pragma unroll 4
    for (int c = 0; c < 64; c++) {
        ulonglong2 wA = s_eA[c];   // {wl, wr}
        ulonglong2 wB = s_eB[c];   // {we, b}
        u64 mm = s_m[c];
        unsigned mlo = (unsigned)mm, mhi = (unsigned)(mm >> 32);
#pragma unroll
        for (int k = 0; k < EPT; k++) {
            u64 z = fma2(a2[k], wB.x, wB.y);
            z = fma2(t2[k], wA.y, z);
            z = fma2(s2[k], wA.x, z);
            acc[k] = add2(acc[k], abso2(z, mlo, mhi));
        }
    }

    u64 P = g_lin[0], Q = g_lin[1], R = g_lin[2], B = g_lin[3];
#pragma unroll
    for (int k = 0; k < EPT; k++) {
        if (!ok[k]) continue;
        u64 f2 = add2(acc[k], B);
        f2 = fma2(a2[k], R, f2);
        f2 = fma2(t2[k], Q, f2);
        f2 = fma2(s2[k], P, f2);
        float f0, f1; unpack2(f2, f0, f1);
        float e0 = ex2f(f0), e1 = ex2f(f1);
        atomicAdd(&g_degattr[dsti[k]], make_float2(1.0f, av[k]));
        atomicAdd(&g_accum[dsti[k]], make_float4(e0, e0 * sv[k], e1, e1 * sv[k]));
    }
}

// ---------------------------------------------------------------------------
// launch 4: S[target] + folded constant vector Cv (1 block, 128 threads)
__global__ void k_tgt(const float* __restrict__ x, const int* __restrict__ tgtp)
{
    __shared__ float2 sh_S;
    int tid = threadIdx.x;
    int tgt = tgtp[0];   // low 32 bits valid for int32/int64 (LE)
    if (tid < 32) {
        float s = x[tgt];
        float2 da = g_degattr[tgt];
        float am = da.y / fmaxf(da.x, 1.0f);
        u64 s2 = pack2(s, s), a2 = pack2(am, am);
        u64 acc = 0ull;
        for (int c = tid; c < 64; c += 32) {
            ulonglong2 A = g_nA[c], Bv = g_nB[c];
            u64 z = fma2(a2, A.y, Bv.x);
            z = fma2(s2, A.x, z);
            acc = add2(acc, abso2(z, (unsigned)Bv.y, (unsigned)(Bv.y >> 32)));
        }
        float h0, h1; unpack2(acc, h0, h1);
#pragma unroll
        for (int off = 16; off > 0; off >>= 1) {
            h0 += __shfl_xor_sync(0xffffffffu, h0, off);
            h1 += __shfl_xor_sync(0xffffffffu, h1, off);
        }
        u64 f = add2(pack2(h0, h1), fma2(s2, g_nlpq, fma2(a2, g_nlr, g_nlb)));
        float f0, f1; unpack2(f, f0, f1);
        float e0 = ex2f(f0), e1 = ex2f(f1);
        float4 ac = g_accum[tgt];
        if (tid == 0)
            sh_S = make_float2((ac.y + e0 * s) / (ac.x + e0),
                               (ac.w + e1 * s) / (ac.z + e1));
    }
    __syncthreads();
    float2 st = sh_S;
    if (tid < 128)
        g_Cv[tid] = fmaf(st.x, g_D0[tid], fmaf(st.y, g_D1[tid], g_CB[tid]));
}

// ---------------------------------------------------------------------------
// launch 5: fused self-loop/softmax finalize + output write.
// Phase 1: thread per node computes S -> smem. Phase 2: warp streams 32 nodes.
__global__ void __launch_bounds__(256) k_nodes_out(
    const float* __restrict__ x, int n, float* __restrict__ out)
{
    __shared__ ulonglong2 s_A[64], s_B[64];
    __shared__ float2 s_S[256];
    int tid = threadIdx.x;
    if (tid < 64) { s_A[tid] = g_nA[tid]; s_B[tid] = g_nB[tid]; }
    __syncthreads();

    int i = blockIdx.x * 256 + tid;
    int ii = (i < n) ? i : (n - 1);
    {
        float s = x[ii];
        float2 da = g_degattr[ii];
        float am = da.y / fmaxf(da.x, 1.0f);
        u64 s2 = pack2(s, s), a2 = pack2(am, am);
        u64 accE = 0ull, accO = 0ull;
#pragma unroll 4
        for (int c = 0; c < 64; c += 2) {
            ulonglong2 A0 = s_A[c],     B0 = s_B[c];
            ulonglong2 A1 = s_A[c + 1], B1 = s_B[c + 1];
            u64 z0 = fma2(a2, A0.y, B0.x); z0 = fma2(s2, A0.x, z0);
            u64 z1 = fma2(a2, A1.y, B1.x); z1 = fma2(s2, A1.x, z1);
            accE = add2(accE, abso2(z0, (unsigned)B0.y, (unsigned)(B0.y >> 32)));
            accO = add2(accO, abso2(z1, (unsigned)B1.y, (unsigned)(B1.y >> 32)));
        }
        u64 f = add2(add2(accE, accO), fma2(s2, g_nlpq, fma2(a2, g_nlr, g_nlb)));
        float f0, f1; unpack2(f, f0, f1);
        float e0 = ex2f(f0), e1 = ex2f(f1);
        float4 ac = g_accum[ii];
        s_S[tid] = make_float2((ac.y + e0 * s) / (ac.x + e0),
                               (ac.w + e1 * s) / (ac.z + e1));
    }
    __syncthreads();

    int lane = tid & 31, w = tid >> 5;
    float4 A0v = ((const float4*)g_A0)[lane];
    float4 A1v = ((const float4*)g_A1)[lane];
    float4 Cv  = ((const float4*)g_Cv)[lane];
    int base = blockIdx.x * 256 + w * 32;
    float4* o4 = (float4*)out;
#pragma unroll 4
    for (int j = 0; j < 32; j++) {
        int node = base + j;
        if (node >= n) break;
        float2 sS = s_S[w * 32 + j];
        float4 o;
        o.x = fmaf(sS.x, A0v.x, fmaf(sS.y, A1v.x, Cv.x));
        o.y = fmaf(sS.x, A0v.y, fmaf(sS.y, A1v.y, Cv.y));
        o.z = fmaf(sS.x, A0v.z, fmaf(sS.y, A1v.z, Cv.z));
        o.w = fmaf(sS.x, A0v.w, fmaf(sS.y, A1v.w, Cv.w));
        o4[(long long)node * 32 + lane] = o;
    }
}

// ---------------------------------------------------------------------------
extern "C" void kernel_launch(void* const* d_in, const int* in_sizes, int n_in,
                              void* d_out, int out_size)
{
    const float* x     = (const float*)d_in[0];
    const void*  eidx  = d_in[1];
    const float* eattr = (const float*)d_in[2];
    const int*   tgtp  = (const int*)d_in[3];
    const float* Wl    = (const float*)d_in[4];
    const float* bl    = (const float*)d_in[5];
    const float* Wr    = (const float*)d_in[6];
    const float* br    = (const float*)d_in[7];
    const float* We    = (const float*)d_in[8];
    const float* att   = (const float*)d_in[9];
    const float* bout  = (const float*)d_in[10];
    const float* Wfc   = (const float*)d_in[11];
    const float* bfc   = (const float*)d_in[12];

    int n = in_sizes[0];   // N nodes (x is [N,1])
    int E = in_sizes[2];   // edges (edge_attr is [E,1])
    float* out = (float*)d_out;

    int nblk = (n + 255) / 256;
    k_zero<<<nblk, 256>>>(n);                                    // idx 0
    k_wprep<<<1, 128>>>(eidx, n, Wl, bl, Wr, br, We, att);       // idx 1
    k_vecA<<<16, 256>>>(Wl, bl, bout, Wfc, bfc);                 // idx 2
    int ethreads = (E + EPT - 1) / EPT;
    k_edges<<<(ethreads + 255) / 256, 256>>>(x, eidx, eattr, E); // idx 3 (profiled)
    k_tgt<<<1, 128>>>(x, tgtp);                                  // idx 4
    k_nodes_out<<<nblk, 256>>>(x, n, out);                       // idx 5
}